// round 1
// baseline (speedup 1.0000x reference)
#include <cuda_runtime.h>
#include <math.h>

// Problem constants
#define NTOK 8192     // B*T = 4*2048
#define CDIM 1024
#define HDIM 2048
#define NEXP 8
#define NPAIR (NTOK * 2)   // top-2 -> exactly 2 pairs per token

// GEMM tiling
#define BM 128
#define BN 128
#define BK 8
#define MT_MAX 136    // sum ceil(cnt_e/128) <= P/128 + E = 136

// ---------------- scratch (static device globals; no allocation at launch) ----
__device__ float g_h[(size_t)NPAIR * HDIM];   // 128 MB: gate then silu(gate)*up
__device__ float g_y[(size_t)NPAIR * CDIM];   //  64 MB: per-pair expert output
__device__ int   g_sel[NTOK * 2];             // top-2 expert ids per token
__device__ float g_selw[NTOK * 2];            // top-2 gate probs per token
__device__ int   g_tok[NPAIR];                // token id per pair (sorted by expert)
__device__ float g_wt[NPAIR];                 // combine weight per pair
__device__ int   g_pairidx[NTOK * 2];         // pair index for (token, slot)
__device__ int   g_cnt[NEXP];
__device__ int   g_off[NEXP];
__device__ int   g_tileE[MT_MAX];
__device__ int   g_tileR[MT_MAX];
__device__ int   g_numTiles;

// ---------------- gating: logits -> softmax -> top2 --------------------------
__global__ void gate_kernel(const float* __restrict__ x,
                            const float* __restrict__ wgate) {
    int warp = (blockIdx.x * blockDim.x + threadIdx.x) >> 5;
    int lane = threadIdx.x & 31;
    if (warp >= NTOK) return;
    const float* xr = x + (size_t)warp * CDIM;

    float acc[NEXP];
#pragma unroll
    for (int e = 0; e < NEXP; e++) acc[e] = 0.f;

    for (int i = lane * 4; i < CDIM; i += 128) {
        float4 xv = *(const float4*)(xr + i);
        float xs[4] = {xv.x, xv.y, xv.z, xv.w};
#pragma unroll
        for (int j = 0; j < 4; j++) {
            const float* wr = wgate + (size_t)(i + j) * NEXP;
#pragma unroll
            for (int e = 0; e < NEXP; e++) acc[e] += xs[j] * wr[e];
        }
    }
#pragma unroll
    for (int e = 0; e < NEXP; e++)
#pragma unroll
        for (int d = 16; d > 0; d >>= 1)
            acc[e] += __shfl_down_sync(0xffffffffu, acc[e], d);

    if (lane == 0) {
        float m = acc[0];
#pragma unroll
        for (int e = 1; e < NEXP; e++) m = fmaxf(m, acc[e]);
        float p[NEXP];
        float s = 0.f;
#pragma unroll
        for (int e = 0; e < NEXP; e++) { p[e] = expf(acc[e] - m); s += p[e]; }
        float inv = 1.f / s;
#pragma unroll
        for (int e = 0; e < NEXP; e++) p[e] *= inv;

        int i1 = 0;
#pragma unroll
        for (int e = 1; e < NEXP; e++) if (p[e] > p[i1]) i1 = e;   // strict > : ties to lower index (jax top_k)
        int i2 = (i1 == 0) ? 1 : 0;
#pragma unroll
        for (int e = 0; e < NEXP; e++) if (e != i1 && p[e] > p[i2]) i2 = e;

        g_sel[2 * warp]      = i1;  g_selw[2 * warp]      = p[i1];
        g_sel[2 * warp + 1]  = i2;  g_selw[2 * warp + 1]  = p[i2];
    }
}

// ---------------- deterministic routing build (single block) -----------------
__global__ void setup_kernel() {
    __shared__ int scnt[NEXP];
    __shared__ int soff[NEXP];
    __shared__ int wsum[8];
    __shared__ int carry_s;
    int tid = threadIdx.x, lane = tid & 31, wid = tid >> 5;

    if (tid < NEXP) scnt[tid] = 0;
    __syncthreads();
    for (int t = tid; t < NTOK; t += 256) {
        atomicAdd(&scnt[g_sel[2 * t]], 1);
        atomicAdd(&scnt[g_sel[2 * t + 1]], 1);
    }
    __syncthreads();
    if (tid == 0) {
        int o = 0, nt = 0;
        for (int e = 0; e < NEXP; e++) {
            g_cnt[e] = scnt[e]; g_off[e] = o; soff[e] = o;
            for (int r = 0; r < scnt[e]; r += BM) {
                g_tileE[nt] = e; g_tileR[nt] = r; nt++;
            }
            o += scnt[e];
        }
        g_numTiles = nt;
    }
    __syncthreads();

    // Per-expert stable (token-order) placement via block prefix scans.
    for (int e = 0; e < NEXP; e++) {
        if (tid == 0) carry_s = 0;
        __syncthreads();
        int base_off = soff[e];
        for (int base = 0; base < NTOK; base += 256) {
            int t = base + tid;
            int slot = (g_sel[2 * t] == e) ? 0 : ((g_sel[2 * t + 1] == e) ? 1 : -1);
            int f = (slot >= 0) ? 1 : 0;
            int v = f;
#pragma unroll
            for (int d = 1; d < 32; d <<= 1) {
                int u = __shfl_up_sync(0xffffffffu, v, d);
                if (lane >= d) v += u;
            }
            if (lane == 31) wsum[wid] = v;
            __syncthreads();
            int wbase = 0, tot = 0;
#pragma unroll
            for (int w = 0; w < 8; w++) { if (w < wid) wbase += wsum[w]; tot += wsum[w]; }
            if (f) {
                int p = base_off + carry_s + wbase + v - 1;   // exclusive rank
                g_tok[p] = t;
                g_wt[p]  = g_selw[2 * t + slot];
                g_pairidx[2 * t + slot] = p;
            }
            __syncthreads();
            if (tid == 0) carry_s += tot;
            __syncthreads();
        }
    }
}

// ---------------- tiled fp32 GEMM over expert-grouped rows -------------------
// mode 0: gate pass   A = gathered x rows, B = wg[e], store acc -> g_h
// mode 1: up pass     A = gathered x rows, B = wi[e], g_h = silu(g_h) * acc
// mode 2: down pass   A = g_h rows (contiguous), B = wo[e], store acc -> g_y
__global__ void __launch_bounds__(256)
gemm_kernel(const float* __restrict__ X, const float* __restrict__ Bw,
            int Kdim, int Ncols, int mode) {
    int bx = blockIdx.x;
    if (bx >= g_numTiles) return;
    int by = blockIdx.y;
    int e  = g_tileE[bx];
    int r0 = g_tileR[bx];
    int off = g_off[e];
    int rowsLeft = g_cnt[e] - r0;

    const float* Bp = Bw + (size_t)e * Kdim * Ncols + (size_t)by * BN;

    __shared__ float As[BK][BM];
    __shared__ float Bs[BK][BN];

    int tid = threadIdx.x;
    int ar = tid >> 1;
    int ac = (tid & 1) * 4;
    bool avalid = ar < rowsLeft;
    const float* Ap = X;  // dummy init
    if (avalid) {
        if (mode < 2) Ap = X + (size_t)g_tok[off + r0 + ar] * CDIM + ac;
        else          Ap = g_h + (size_t)(off + r0 + ar) * HDIM + ac;
    }
    int br = tid >> 5;
    int bc = (tid & 31) * 4;

    int tx = tid & 15, ty = tid >> 4;
    float acc[8][8];
#pragma unroll
    for (int i = 0; i < 8; i++)
#pragma unroll
        for (int j = 0; j < 8; j++) acc[i][j] = 0.f;

    for (int k0 = 0; k0 < Kdim; k0 += BK) {
        float4 av = make_float4(0.f, 0.f, 0.f, 0.f);
        if (avalid) av = *(const float4*)(Ap + k0);
        As[ac + 0][ar] = av.x;
        As[ac + 1][ar] = av.y;
        As[ac + 2][ar] = av.z;
        As[ac + 3][ar] = av.w;
        float4 bv = *(const float4*)(Bp + (size_t)(k0 + br) * Ncols + bc);
        *(float4*)&Bs[br][bc] = bv;
        __syncthreads();
#pragma unroll
        for (int k = 0; k < BK; k++) {
            float a[8], b[8];
            *(float4*)&a[0] = *(const float4*)&As[k][ty * 4];
            *(float4*)&a[4] = *(const float4*)&As[k][64 + ty * 4];
            *(float4*)&b[0] = *(const float4*)&Bs[k][tx * 4];
            *(float4*)&b[4] = *(const float4*)&Bs[k][64 + tx * 4];
#pragma unroll
            for (int i = 0; i < 8; i++)
#pragma unroll
                for (int j = 0; j < 8; j++)
                    acc[i][j] += a[i] * b[j];
        }
        __syncthreads();
    }

#pragma unroll
    for (int i = 0; i < 8; i++) {
        int m = (i < 4) ? (ty * 4 + i) : (64 + ty * 4 + i - 4);
        if (m >= rowsLeft) continue;
        size_t rowbase;
        if (mode < 2) rowbase = (size_t)(off + r0 + m) * HDIM + (size_t)by * BN;
        else          rowbase = (size_t)(off + r0 + m) * CDIM + (size_t)by * BN;
#pragma unroll
        for (int h = 0; h < 2; h++) {
            int n = h * 64 + tx * 4;
            float4 v;
            v.x = acc[i][h * 4 + 0];
            v.y = acc[i][h * 4 + 1];
            v.z = acc[i][h * 4 + 2];
            v.w = acc[i][h * 4 + 3];
            if (mode == 0) {
                *(float4*)&g_h[rowbase + n] = v;
            } else if (mode == 1) {
                float4 g = *(const float4*)&g_h[rowbase + n];
                v.x *= g.x / (1.f + expf(-g.x));
                v.y *= g.y / (1.f + expf(-g.y));
                v.z *= g.z / (1.f + expf(-g.z));
                v.w *= g.w / (1.f + expf(-g.w));
                *(float4*)&g_h[rowbase + n] = v;
            } else {
                *(float4*)&g_y[rowbase + n] = v;
            }
        }
    }
}

// ---------------- final combine: out[t] = w0*y[p0] + w1*y[p1] ----------------
__global__ void combine_kernel(float* __restrict__ out) {
    int gid = blockIdx.x * blockDim.x + threadIdx.x;   // over NTOK * CDIM/4
    int t  = gid >> 8;            // CDIM/4 = 256
    int c4 = (gid & 255) * 4;
    int p0 = g_pairidx[2 * t], p1 = g_pairidx[2 * t + 1];
    float w0 = g_wt[p0], w1 = g_wt[p1];
    float4 y0 = *(const float4*)&g_y[(size_t)p0 * CDIM + c4];
    float4 y1 = *(const float4*)&g_y[(size_t)p1 * CDIM + c4];
    float4 o;
    o.x = w0 * y0.x + w1 * y1.x;
    o.y = w0 * y0.y + w1 * y1.y;
    o.z = w0 * y0.z + w1 * y1.z;
    o.w = w0 * y0.w + w1 * y1.w;
    *(float4*)(out + (size_t)t * CDIM + c4) = o;
}

// ---------------- launch -----------------------------------------------------
extern "C" void kernel_launch(void* const* d_in, const int* in_sizes, int n_in,
                              void* d_out, int out_size) {
    const float* x      = (const float*)d_in[0];   // [B,T,C]
    const float* w_gate = (const float*)d_in[1];   // [C,E]
    const float* wi     = (const float*)d_in[2];   // [E,C,H]
    const float* wg     = (const float*)d_in[3];   // [E,C,H]
    const float* wo     = (const float*)d_in[4];   // [E,H,C]
    float* out = (float*)d_out;

    gate_kernel<<<NTOK / 8, 256>>>(x, w_gate);
    setup_kernel<<<1, 256>>>();

    dim3 g1(MT_MAX, HDIM / BN);
    gemm_kernel<<<g1, 256>>>(x, wg, CDIM, HDIM, 0);   // gate = x @ wg[e]
    gemm_kernel<<<g1, 256>>>(x, wi, CDIM, HDIM, 1);   // h = silu(gate) * (x @ wi[e])
    dim3 g2(MT_MAX, CDIM / BN);
    gemm_kernel<<<g2, 256>>>(nullptr, wo, HDIM, CDIM, 2);  // y = h @ wo[e]

    combine_kernel<<<NTOK * (CDIM / 4) / 256, 256>>>(out);
}

// round 6
// speedup vs baseline: 1.8412x; 1.8412x over previous
#include <cuda_runtime.h>
#include <cuda_bf16.h>
#include <cstdint>
#include <math.h>

// ---------------- problem constants ------------------------------------------
#define NTOK 8192
#define CDIM 1024
#define HDIM 2048
#define NEXP 8
#define NPAIR (NTOK * 2)
#define BM 128
#define MT_MAX 136

// ---------------- scratch ----------------------------------------------------
__device__ __nv_bfloat16 g_axh[(size_t)NPAIR * CDIM];
__device__ __nv_bfloat16 g_axl[(size_t)NPAIR * CDIM];
__device__ __nv_bfloat16 g_wgTh[(size_t)NEXP * HDIM * CDIM];
__device__ __nv_bfloat16 g_wgTl[(size_t)NEXP * HDIM * CDIM];
__device__ __nv_bfloat16 g_wiTh[(size_t)NEXP * HDIM * CDIM];
__device__ __nv_bfloat16 g_wiTl[(size_t)NEXP * HDIM * CDIM];
__device__ __nv_bfloat16 g_woTh[(size_t)NEXP * CDIM * HDIM];
__device__ __nv_bfloat16 g_woTl[(size_t)NEXP * CDIM * HDIM];
__device__ float         g_gf[(size_t)NPAIR * HDIM];
__device__ __nv_bfloat16 g_hh[(size_t)NPAIR * HDIM];
__device__ __nv_bfloat16 g_hl[(size_t)NPAIR * HDIM];
__device__ float         g_y[(size_t)NPAIR * CDIM];

__device__ int   g_sel[NTOK * 2];
__device__ float g_selw[NTOK * 2];
__device__ int   g_tok[NPAIR];
__device__ float g_wt[NPAIR];
__device__ int   g_pairidx[NTOK * 2];
__device__ int   g_cnt[NEXP];
__device__ int   g_off[NEXP];
__device__ int   g_tileE[MT_MAX];
__device__ int   g_tileR[MT_MAX];
__device__ int   g_numTiles;

// ---------------- mma.sync bf16 ----------------------------------------------
__device__ __forceinline__ void mma16816(float* d, const uint32_t* a, uint32_t b0, uint32_t b1) {
    asm volatile("mma.sync.aligned.m16n8k16.row.col.f32.bf16.bf16.f32 "
                 "{%0,%1,%2,%3}, {%4,%5,%6,%7}, {%8,%9}, {%0,%1,%2,%3};"
                 : "+f"(d[0]), "+f"(d[1]), "+f"(d[2]), "+f"(d[3])
                 : "r"(a[0]), "r"(a[1]), "r"(a[2]), "r"(a[3]), "r"(b0), "r"(b1));
}

// ---------------- gating -----------------------------------------------------
__global__ void gate_kernel(const float* __restrict__ x, const float* __restrict__ wgate) {
    int warp = (blockIdx.x * blockDim.x + threadIdx.x) >> 5;
    int lane = threadIdx.x & 31;
    if (warp >= NTOK) return;
    const float* xr = x + (size_t)warp * CDIM;
    float acc[NEXP];
#pragma unroll
    for (int e = 0; e < NEXP; e++) acc[e] = 0.f;
    for (int i = lane * 4; i < CDIM; i += 128) {
        float4 xv = *(const float4*)(xr + i);
        float xs[4] = {xv.x, xv.y, xv.z, xv.w};
#pragma unroll
        for (int j = 0; j < 4; j++) {
            const float* wr = wgate + (size_t)(i + j) * NEXP;
#pragma unroll
            for (int e = 0; e < NEXP; e++) acc[e] += xs[j] * wr[e];
        }
    }
#pragma unroll
    for (int e = 0; e < NEXP; e++)
#pragma unroll
        for (int d = 16; d > 0; d >>= 1) acc[e] += __shfl_down_sync(0xffffffffu, acc[e], d);
    if (lane == 0) {
        float m = acc[0];
#pragma unroll
        for (int e = 1; e < NEXP; e++) m = fmaxf(m, acc[e]);
        float p[NEXP]; float s = 0.f;
#pragma unroll
        for (int e = 0; e < NEXP; e++) { p[e] = expf(acc[e] - m); s += p[e]; }
        float inv = 1.f / s;
#pragma unroll
        for (int e = 0; e < NEXP; e++) p[e] *= inv;
        int i1 = 0;
#pragma unroll
        for (int e = 1; e < NEXP; e++) if (p[e] > p[i1]) i1 = e;
        int i2 = (i1 == 0) ? 1 : 0;
#pragma unroll
        for (int e = 0; e < NEXP; e++) if (e != i1 && p[e] > p[i2]) i2 = e;
        g_sel[2 * warp] = i1;     g_selw[2 * warp] = p[i1];
        g_sel[2 * warp + 1] = i2; g_selw[2 * warp + 1] = p[i2];
    }
}

// ---------------- routing build ----------------------------------------------
__global__ void setup_kernel() {
    __shared__ int scnt[NEXP], soff[NEXP], wsum[8];
    __shared__ int carry_s;
    int tid = threadIdx.x, lane = tid & 31, wid = tid >> 5;
    if (tid < NEXP) scnt[tid] = 0;
    __syncthreads();
    for (int t = tid; t < NTOK; t += 256) {
        atomicAdd(&scnt[g_sel[2 * t]], 1);
        atomicAdd(&scnt[g_sel[2 * t + 1]], 1);
    }
    __syncthreads();
    if (tid == 0) {
        int o = 0, nt = 0;
        for (int e = 0; e < NEXP; e++) {
            g_cnt[e] = scnt[e]; g_off[e] = o; soff[e] = o;
            for (int r = 0; r < scnt[e]; r += BM) { g_tileE[nt] = e; g_tileR[nt] = r; nt++; }
            o += scnt[e];
        }
        g_numTiles = nt;
    }
    __syncthreads();
    for (int e = 0; e < NEXP; e++) {
        if (tid == 0) carry_s = 0;
        __syncthreads();
        int base_off = soff[e];
        for (int base = 0; base < NTOK; base += 256) {
            int t = base + tid;
            int slot = (g_sel[2 * t] == e) ? 0 : ((g_sel[2 * t + 1] == e) ? 1 : -1);
            int f = (slot >= 0) ? 1 : 0;
            int v = f;
#pragma unroll
            for (int d = 1; d < 32; d <<= 1) {
                int u = __shfl_up_sync(0xffffffffu, v, d);
                if (lane >= d) v += u;
            }
            if (lane == 31) wsum[wid] = v;
            __syncthreads();
            int wbase = 0, tot = 0;
#pragma unroll
            for (int w = 0; w < 8; w++) { if (w < wid) wbase += wsum[w]; tot += wsum[w]; }
            if (f) {
                int p = base_off + carry_s + wbase + v - 1;
                g_tok[p] = t;
                g_wt[p] = g_selw[2 * t + slot];
                g_pairidx[2 * t + slot] = p;
            }
            __syncthreads();
            if (tid == 0) carry_s += tot;
            __syncthreads();
        }
    }
}

// ---------------- weight transpose + split to hi/lo planes --------------------
// FIX (R6): destination __device__ arrays selected INSIDE device code via
// template index — never pass a __device__ symbol as a host-side kernel arg
// (the host shadow address is ATS-dereferenceable on GB300, so R3-R5 silently
// wrote weights to host memory and computed on zeros).
// src [E][K][S] fp32 -> dsth/dstl [E][S][K] bf16
template <int W>
__global__ void tsplit_kernel(const float* __restrict__ src, int K, int S) {
    __nv_bfloat16* dsth = (W == 0) ? g_wgTh : (W == 1) ? g_wiTh : g_woTh;
    __nv_bfloat16* dstl = (W == 0) ? g_wgTl : (W == 1) ? g_wiTl : g_woTl;
    __shared__ float t[32][33];
    int e = blockIdx.z;
    int k0 = blockIdx.x * 32, s0 = blockIdx.y * 32;
    const float* sp = src + (size_t)e * K * S;
    int tx = threadIdx.x, ty = threadIdx.y;
#pragma unroll
    for (int j = 0; j < 32; j += 8)
        t[ty + j][tx] = sp[(size_t)(k0 + ty + j) * S + s0 + tx];
    __syncthreads();
    size_t dbase = (size_t)e * S * K;
#pragma unroll
    for (int j = 0; j < 32; j += 8) {
        float v = t[tx][ty + j];
        __nv_bfloat16 hi = __float2bfloat16(v);
        __nv_bfloat16 lo = __float2bfloat16(v - __bfloat162float(hi));
        size_t o = dbase + (size_t)(s0 + ty + j) * K + k0 + tx;
        dsth[o] = hi; dstl[o] = lo;
    }
}

// ---------------- activation gather + split -----------------------------------
__global__ void gather_split_kernel(const float* __restrict__ x) {
    int p = blockIdx.x;
    int t = g_tok[p];
    const float* src = x + (size_t)t * CDIM;
    size_t dst = (size_t)p * CDIM;
    for (int i = threadIdx.x; i < CDIM; i += 256) {
        float v = src[i];
        __nv_bfloat16 hi = __float2bfloat16(v);
        g_axh[dst + i] = hi;
        g_axl[dst + i] = __float2bfloat16(v - __bfloat162float(hi));
    }
}

// ---------------- split-bf16 mma GEMM: tile 128x64, BK=32 ---------------------
// Plain uint4 global->shared fills, plain u32 LDS fragment loads.
// MODE 0: gate = ax @ wgT^T -> g_gf (fp32)
// MODE 1: up   = ax @ wiT^T; h = silu(g_gf)*up -> g_hh/g_hl
// MODE 2: y    = h  @ woT^T -> g_y (fp32)
#define ROWH 40

template <int MODE>
__global__ void __launch_bounds__(256)
moe_mma() {
    constexpr int K = (MODE == 2) ? HDIM : CDIM;

    __shared__ __align__(16) __nv_bfloat16 sAh[128 * ROWH];
    __shared__ __align__(16) __nv_bfloat16 sAl[128 * ROWH];
    __shared__ __align__(16) __nv_bfloat16 sBh[64 * ROWH];
    __shared__ __align__(16) __nv_bfloat16 sBl[64 * ROWH];

    int bx = blockIdx.x;
    if (bx >= g_numTiles) return;
    int by = blockIdx.y;
    int e = g_tileE[bx], r0 = g_tileR[bx], off = g_off[e];
    int rowsLeft = g_cnt[e] - r0;
    if (rowsLeft > 128) rowsLeft = 128;
    int nb = by * 64;

    int tid = threadIdx.x, wid = tid >> 5, lane = tid & 31;
    int WM = wid >> 1, WN = wid & 1;       // 4x2 warp grid over 128x64
    int gq = lane >> 2, tg = lane & 3;     // fragment group / thread-in-group

    const __nv_bfloat16 *A_h, *A_l, *B_h, *B_l;
    if (MODE == 0) {
        A_h = g_axh + (size_t)(off + r0) * CDIM;
        A_l = g_axl + (size_t)(off + r0) * CDIM;
        B_h = g_wgTh + ((size_t)e * HDIM + nb) * CDIM;
        B_l = g_wgTl + ((size_t)e * HDIM + nb) * CDIM;
    } else if (MODE == 1) {
        A_h = g_axh + (size_t)(off + r0) * CDIM;
        A_l = g_axl + (size_t)(off + r0) * CDIM;
        B_h = g_wiTh + ((size_t)e * HDIM + nb) * CDIM;
        B_l = g_wiTl + ((size_t)e * HDIM + nb) * CDIM;
    } else {
        A_h = g_hh + (size_t)(off + r0) * HDIM;
        A_l = g_hl + (size_t)(off + r0) * HDIM;
        B_h = g_woTh + ((size_t)e * CDIM + nb) * HDIM;
        B_l = g_woTl + ((size_t)e * CDIM + nb) * HDIM;
    }

    float acc[2][4][4];
#pragma unroll
    for (int a = 0; a < 2; a++)
#pragma unroll
        for (int b = 0; b < 4; b++)
#pragma unroll
            for (int c = 0; c < 4; c++) acc[a][b][c] = 0.f;

    const uint4 zero4 = make_uint4(0u, 0u, 0u, 0u);

    for (int k0 = 0; k0 < K; k0 += 32) {
        // ---- fill A: 2 planes x 128 rows x 4 chunks(16B) = 1024; 4/thread ----
#pragma unroll
        for (int i = 0; i < 4; i++) {
            int idx = tid + 256 * i;
            int p = idx >> 9;
            int rem = idx & 511;
            int row = rem >> 2;
            int ch = rem & 3;
            const __nv_bfloat16* src = p ? A_l : A_h;
            __nv_bfloat16* dst = p ? sAl : sAh;
            uint4 v = zero4;
            if (row < rowsLeft)
                v = *(const uint4*)(src + (size_t)row * K + k0 + ch * 8);
            *(uint4*)(dst + row * ROWH + ch * 8) = v;
        }
        // ---- fill B: 2 planes x 64 rows x 4 chunks = 512; 2/thread ----------
#pragma unroll
        for (int i = 0; i < 2; i++) {
            int idx = tid + 256 * i;
            int p = idx >> 8;
            int rem = idx & 255;
            int row = rem >> 2;
            int ch = rem & 3;
            const __nv_bfloat16* src = p ? B_l : B_h;
            __nv_bfloat16* dst = p ? sBl : sBh;
            uint4 v = *(const uint4*)(src + (size_t)row * K + k0 + ch * 8);
            *(uint4*)(dst + row * ROWH + ch * 8) = v;
        }
        __syncthreads();

#pragma unroll
        for (int ks = 0; ks < 2; ks++) {
            int kh = ks * 16;
            uint32_t ah[2][4], al[2][4], bh[4][2], bl[4][2];
#pragma unroll
            for (int mi = 0; mi < 2; mi++) {
                int rb = WM * 32 + mi * 16;
                ah[mi][0] = *(const uint32_t*)(sAh + (rb + gq) * ROWH + kh + tg * 2);
                ah[mi][1] = *(const uint32_t*)(sAh + (rb + gq + 8) * ROWH + kh + tg * 2);
                ah[mi][2] = *(const uint32_t*)(sAh + (rb + gq) * ROWH + kh + 8 + tg * 2);
                ah[mi][3] = *(const uint32_t*)(sAh + (rb + gq + 8) * ROWH + kh + 8 + tg * 2);
                al[mi][0] = *(const uint32_t*)(sAl + (rb + gq) * ROWH + kh + tg * 2);
                al[mi][1] = *(const uint32_t*)(sAl + (rb + gq + 8) * ROWH + kh + tg * 2);
                al[mi][2] = *(const uint32_t*)(sAl + (rb + gq) * ROWH + kh + 8 + tg * 2);
                al[mi][3] = *(const uint32_t*)(sAl + (rb + gq + 8) * ROWH + kh + 8 + tg * 2);
            }
#pragma unroll
            for (int nj = 0; nj < 4; nj++) {
                int nbr = WN * 32 + nj * 8;
                bh[nj][0] = *(const uint32_t*)(sBh + (nbr + gq) * ROWH + kh + tg * 2);
                bh[nj][1] = *(const uint32_t*)(sBh + (nbr + gq) * ROWH + kh + 8 + tg * 2);
                bl[nj][0] = *(const uint32_t*)(sBl + (nbr + gq) * ROWH + kh + tg * 2);
                bl[nj][1] = *(const uint32_t*)(sBl + (nbr + gq) * ROWH + kh + 8 + tg * 2);
            }
#pragma unroll
            for (int mi = 0; mi < 2; mi++)
#pragma unroll
                for (int nj = 0; nj < 4; nj++) {
                    mma16816(acc[mi][nj], ah[mi], bh[nj][0], bh[nj][1]);
                    mma16816(acc[mi][nj], al[mi], bh[nj][0], bh[nj][1]);
                    mma16816(acc[mi][nj], ah[mi], bl[nj][0], bl[nj][1]);
                }
        }
        __syncthreads();
    }

    // ---- epilogue ----
    int grb = off + r0;
#pragma unroll
    for (int mi = 0; mi < 2; mi++) {
#pragma unroll
        for (int half = 0; half < 2; half++) {
            int r = WM * 32 + mi * 16 + gq + half * 8;
            if (r >= rowsLeft) continue;
            size_t grow = (size_t)(grb + r);
#pragma unroll
            for (int nj = 0; nj < 4; nj++) {
                int c = nb + WN * 32 + nj * 8 + tg * 2;
                float d0 = acc[mi][nj][half * 2 + 0];
                float d1 = acc[mi][nj][half * 2 + 1];
                if (MODE == 0) {
                    *(float2*)&g_gf[grow * HDIM + c] = make_float2(d0, d1);
                } else if (MODE == 1) {
                    float2 gt = *(const float2*)&g_gf[grow * HDIM + c];
                    float h0 = d0 * gt.x / (1.f + expf(-gt.x));
                    float h1 = d1 * gt.y / (1.f + expf(-gt.y));
                    __nv_bfloat16 h0h = __float2bfloat16(h0);
                    __nv_bfloat16 h1h = __float2bfloat16(h1);
                    __nv_bfloat16 h0l = __float2bfloat16(h0 - __bfloat162float(h0h));
                    __nv_bfloat16 h1l = __float2bfloat16(h1 - __bfloat162float(h1h));
                    uint32_t uh = ((uint32_t)__bfloat16_as_ushort(h1h) << 16) | __bfloat16_as_ushort(h0h);
                    uint32_t ul = ((uint32_t)__bfloat16_as_ushort(h1l) << 16) | __bfloat16_as_ushort(h0l);
                    *(uint32_t*)&g_hh[grow * HDIM + c] = uh;
                    *(uint32_t*)&g_hl[grow * HDIM + c] = ul;
                } else {
                    *(float2*)&g_y[grow * CDIM + c] = make_float2(d0, d1);
                }
            }
        }
    }
}

// ---------------- combine ----------------------------------------------------
__global__ void combine_kernel(float* __restrict__ out) {
    int gid = blockIdx.x * blockDim.x + threadIdx.x;
    int t = gid >> 8;
    int c4 = (gid & 255) * 4;
    int p0 = g_pairidx[2 * t], p1 = g_pairidx[2 * t + 1];
    float w0 = g_wt[p0], w1 = g_wt[p1];
    float4 y0 = *(const float4*)&g_y[(size_t)p0 * CDIM + c4];
    float4 y1 = *(const float4*)&g_y[(size_t)p1 * CDIM + c4];
    float4 o;
    o.x = w0 * y0.x + w1 * y1.x;
    o.y = w0 * y0.y + w1 * y1.y;
    o.z = w0 * y0.z + w1 * y1.z;
    o.w = w0 * y0.w + w1 * y1.w;
    *(float4*)(out + (size_t)t * CDIM + c4) = o;
}

// ---------------- launch -----------------------------------------------------
extern "C" void kernel_launch(void* const* d_in, const int* in_sizes, int n_in,
                              void* d_out, int out_size) {
    const float* x      = (const float*)d_in[0];
    const float* w_gate = (const float*)d_in[1];
    const float* wi     = (const float*)d_in[2];
    const float* wg     = (const float*)d_in[3];
    const float* wo     = (const float*)d_in[4];
    float* out = (float*)d_out;

    gate_kernel<<<NTOK / 8, 256>>>(x, w_gate);
    setup_kernel<<<1, 256>>>();
    gather_split_kernel<<<NPAIR, 256>>>(x);

    dim3 tb(32, 8);
    tsplit_kernel<0><<<dim3(CDIM / 32, HDIM / 32, NEXP), tb>>>(wg, CDIM, HDIM);
    tsplit_kernel<1><<<dim3(CDIM / 32, HDIM / 32, NEXP), tb>>>(wi, CDIM, HDIM);
    tsplit_kernel<2><<<dim3(HDIM / 32, CDIM / 32, NEXP), tb>>>(wo, HDIM, CDIM);

    moe_mma<0><<<dim3(MT_MAX, HDIM / 64), 256>>>();
    moe_mma<1><<<dim3(MT_MAX, HDIM / 64), 256>>>();
    moe_mma<2><<<dim3(MT_MAX, CDIM / 64), 256>>>();

    combine_kernel<<<NTOK * (CDIM / 4) / 256, 256>>>(out);
}

// round 7
// speedup vs baseline: 2.1525x; 1.1691x over previous
#include <cuda_runtime.h>
#include <cuda_bf16.h>
#include <cstdint>
#include <math.h>

// ---------------- problem constants ------------------------------------------
#define NTOK 8192
#define CDIM 1024
#define HDIM 2048
#define NEXP 8
#define NPAIR (NTOK * 2)
#define BM 128
#define MT_MAX 136

// ---------------- scratch ----------------------------------------------------
__device__ __nv_bfloat16 g_axh[(size_t)NPAIR * CDIM];
__device__ __nv_bfloat16 g_axl[(size_t)NPAIR * CDIM];
__device__ __nv_bfloat16 g_wgTh[(size_t)NEXP * HDIM * CDIM];
__device__ __nv_bfloat16 g_wgTl[(size_t)NEXP * HDIM * CDIM];
__device__ __nv_bfloat16 g_wiTh[(size_t)NEXP * HDIM * CDIM];
__device__ __nv_bfloat16 g_wiTl[(size_t)NEXP * HDIM * CDIM];
__device__ __nv_bfloat16 g_woTh[(size_t)NEXP * CDIM * HDIM];
__device__ __nv_bfloat16 g_woTl[(size_t)NEXP * CDIM * HDIM];
__device__ __nv_bfloat16 g_hh[(size_t)NPAIR * HDIM];
__device__ __nv_bfloat16 g_hl[(size_t)NPAIR * HDIM];
__device__ float         g_y[(size_t)NPAIR * CDIM];

__device__ int   g_sel[NTOK * 2];
__device__ float g_selw[NTOK * 2];
__device__ int   g_tok[NPAIR];
__device__ float g_wt[NPAIR];
__device__ int   g_pairidx[NTOK * 2];
__device__ int   g_cnt[NEXP];
__device__ int   g_off[NEXP];
__device__ int   g_tileE[MT_MAX];
__device__ int   g_tileR[MT_MAX];
__device__ int   g_numTiles;

// ---------------- PTX helpers -------------------------------------------------
__device__ __forceinline__ uint32_t smem_u32(const void* p) {
    uint32_t a;
    asm("{ .reg .u64 t; cvta.to.shared.u64 t, %1; cvt.u32.u64 %0, t; }" : "=r"(a) : "l"(p));
    return a;
}
__device__ __forceinline__ void ldsm4(uint32_t* r, uint32_t addr) {
    asm volatile("ldmatrix.sync.aligned.m8n8.x4.shared.b16 {%0,%1,%2,%3}, [%4];"
                 : "=r"(r[0]), "=r"(r[1]), "=r"(r[2]), "=r"(r[3]) : "r"(addr));
}
__device__ __forceinline__ void mma16816(float* d, const uint32_t* a, uint32_t b0, uint32_t b1) {
    asm volatile("mma.sync.aligned.m16n8k16.row.col.f32.bf16.bf16.f32 "
                 "{%0,%1,%2,%3}, {%4,%5,%6,%7}, {%8,%9}, {%0,%1,%2,%3};"
                 : "+f"(d[0]), "+f"(d[1]), "+f"(d[2]), "+f"(d[3])
                 : "r"(a[0]), "r"(a[1]), "r"(a[2]), "r"(a[3]), "r"(b0), "r"(b1));
}
#define CP_ASYNC16(dst, src, sz) \
    asm volatile("cp.async.cg.shared.global [%0], [%1], 16, %2;" :: "r"(dst), "l"(src), "r"(sz) : "memory")
#define CP_COMMIT() asm volatile("cp.async.commit_group;" ::: "memory")
#define CP_WAIT(n)  asm volatile("cp.async.wait_group %0;" :: "n"(n) : "memory")

// ---------------- gating -----------------------------------------------------
__global__ void gate_kernel(const float* __restrict__ x, const float* __restrict__ wgate) {
    int warp = (blockIdx.x * blockDim.x + threadIdx.x) >> 5;
    int lane = threadIdx.x & 31;
    if (warp >= NTOK) return;
    const float* xr = x + (size_t)warp * CDIM;
    float acc[NEXP];
#pragma unroll
    for (int e = 0; e < NEXP; e++) acc[e] = 0.f;
    for (int i = lane * 4; i < CDIM; i += 128) {
        float4 xv = *(const float4*)(xr + i);
        float xs[4] = {xv.x, xv.y, xv.z, xv.w};
#pragma unroll
        for (int j = 0; j < 4; j++) {
            const float* wr = wgate + (size_t)(i + j) * NEXP;
#pragma unroll
            for (int e = 0; e < NEXP; e++) acc[e] += xs[j] * wr[e];
        }
    }
#pragma unroll
    for (int e = 0; e < NEXP; e++)
#pragma unroll
        for (int d = 16; d > 0; d >>= 1) acc[e] += __shfl_down_sync(0xffffffffu, acc[e], d);
    if (lane == 0) {
        float m = acc[0];
#pragma unroll
        for (int e = 1; e < NEXP; e++) m = fmaxf(m, acc[e]);
        float p[NEXP]; float s = 0.f;
#pragma unroll
        for (int e = 0; e < NEXP; e++) { p[e] = expf(acc[e] - m); s += p[e]; }
        float inv = 1.f / s;
#pragma unroll
        for (int e = 0; e < NEXP; e++) p[e] *= inv;
        int i1 = 0;
#pragma unroll
        for (int e = 1; e < NEXP; e++) if (p[e] > p[i1]) i1 = e;
        int i2 = (i1 == 0) ? 1 : 0;
#pragma unroll
        for (int e = 0; e < NEXP; e++) if (e != i1 && p[e] > p[i2]) i2 = e;
        g_sel[2 * warp] = i1;     g_selw[2 * warp] = p[i1];
        g_sel[2 * warp + 1] = i2; g_selw[2 * warp + 1] = p[i2];
    }
}

// ---------------- routing build ----------------------------------------------
__global__ void setup_kernel() {
    __shared__ int scnt[NEXP], soff[NEXP], wsum[8];
    __shared__ int carry_s;
    int tid = threadIdx.x, lane = tid & 31, wid = tid >> 5;
    if (tid < NEXP) scnt[tid] = 0;
    __syncthreads();
    for (int t = tid; t < NTOK; t += 256) {
        atomicAdd(&scnt[g_sel[2 * t]], 1);
        atomicAdd(&scnt[g_sel[2 * t + 1]], 1);
    }
    __syncthreads();
    if (tid == 0) {
        int o = 0, nt = 0;
        for (int e = 0; e < NEXP; e++) {
            g_cnt[e] = scnt[e]; g_off[e] = o; soff[e] = o;
            for (int r = 0; r < scnt[e]; r += BM) { g_tileE[nt] = e; g_tileR[nt] = r; nt++; }
            o += scnt[e];
        }
        g_numTiles = nt;
    }
    __syncthreads();
    for (int e = 0; e < NEXP; e++) {
        if (tid == 0) carry_s = 0;
        __syncthreads();
        int base_off = soff[e];
        for (int base = 0; base < NTOK; base += 256) {
            int t = base + tid;
            int slot = (g_sel[2 * t] == e) ? 0 : ((g_sel[2 * t + 1] == e) ? 1 : -1);
            int f = (slot >= 0) ? 1 : 0;
            int v = f;
#pragma unroll
            for (int d = 1; d < 32; d <<= 1) {
                int u = __shfl_up_sync(0xffffffffu, v, d);
                if (lane >= d) v += u;
            }
            if (lane == 31) wsum[wid] = v;
            __syncthreads();
            int wbase = 0, tot = 0;
#pragma unroll
            for (int w = 0; w < 8; w++) { if (w < wid) wbase += wsum[w]; tot += wsum[w]; }
            if (f) {
                int p = base_off + carry_s + wbase + v - 1;
                g_tok[p] = t;
                g_wt[p] = g_selw[2 * t + slot];
                g_pairidx[2 * t + slot] = p;
            }
            __syncthreads();
            if (tid == 0) carry_s += tot;
            __syncthreads();
        }
    }
}

// ---------------- weight transpose + split (device-selected dst) --------------
template <int W>
__global__ void tsplit_kernel(const float* __restrict__ src, int K, int S) {
    __nv_bfloat16* dsth = (W == 0) ? g_wgTh : (W == 1) ? g_wiTh : g_woTh;
    __nv_bfloat16* dstl = (W == 0) ? g_wgTl : (W == 1) ? g_wiTl : g_woTl;
    __shared__ float t[32][33];
    int e = blockIdx.z;
    int k0 = blockIdx.x * 32, s0 = blockIdx.y * 32;
    const float* sp = src + (size_t)e * K * S;
    int tx = threadIdx.x, ty = threadIdx.y;
#pragma unroll
    for (int j = 0; j < 32; j += 8)
        t[ty + j][tx] = sp[(size_t)(k0 + ty + j) * S + s0 + tx];
    __syncthreads();
    size_t dbase = (size_t)e * S * K;
#pragma unroll
    for (int j = 0; j < 32; j += 8) {
        float v = t[tx][ty + j];
        __nv_bfloat16 hi = __float2bfloat16(v);
        __nv_bfloat16 lo = __float2bfloat16(v - __bfloat162float(hi));
        size_t o = dbase + (size_t)(s0 + ty + j) * K + k0 + tx;
        dsth[o] = hi; dstl[o] = lo;
    }
}

// ---------------- activation gather + split -----------------------------------
__global__ void gather_split_kernel(const float* __restrict__ x) {
    int p = blockIdx.x;
    int t = g_tok[p];
    const float* src = x + (size_t)t * CDIM;
    size_t dst = (size_t)p * CDIM;
    for (int i = threadIdx.x; i < CDIM; i += 256) {
        float v = src[i];
        __nv_bfloat16 hi = __float2bfloat16(v);
        g_axh[dst + i] = hi;
        g_axl[dst + i] = __float2bfloat16(v - __bfloat162float(hi));
    }
}

// ---------------- split-bf16 mma GEMM, 128x128 tile, cp.async 2-stage ---------
// MODE 0 (fused): gate = ax@wgT^T, up = ax@wiT^T, h = silu(gate)*up -> g_hh/g_hl
// MODE 2 (down):  y = h@woT^T -> g_y
// 512 threads, warp grid 4m x 4n, warp tile 32x32. Pitch 80 B (conflict-free
// for ldmatrix 8-row groups and for the 16B store pattern).
#define PITCHB 80
#define PLANEB (128 * PITCHB)   // 10240

template <int MODE>
__global__ void __launch_bounds__(512, 1)
moe_mma() {
    constexpr int K = (MODE == 0) ? CDIM : HDIM;
    constexpr int KT = K / 32;
    constexpr int NB = (MODE == 0) ? 4 : 2;       // B plane-tiles per buffer
    constexpr int BUFB = (2 + NB) * PLANEB;       // A(2 planes) + B planes

    extern __shared__ char smem[];
    uint32_t sb = smem_u32(smem);

    int bx = blockIdx.x;
    if (bx >= g_numTiles) return;
    int by = blockIdx.y;
    int e = g_tileE[bx], r0 = g_tileR[bx], off = g_off[e];
    int rowsLeft = g_cnt[e] - r0;
    if (rowsLeft > 128) rowsLeft = 128;
    int nb = by * 128;

    int tid = threadIdx.x, wid = tid >> 5, lane = tid & 31;
    int WM = wid & 3, WN = wid >> 2;              // 4x4 over 128x128
    int gq = lane >> 2, tg = lane & 3;

    // global source pointers per plane slot
    const __nv_bfloat16* srcA[2];
    const __nv_bfloat16* srcB[4];
    if (MODE == 0) {
        srcA[0] = g_axh + (size_t)(off + r0) * CDIM;
        srcA[1] = g_axl + (size_t)(off + r0) * CDIM;
        srcB[0] = g_wgTh + ((size_t)e * HDIM + nb) * CDIM;
        srcB[1] = g_wgTl + ((size_t)e * HDIM + nb) * CDIM;
        srcB[2] = g_wiTh + ((size_t)e * HDIM + nb) * CDIM;
        srcB[3] = g_wiTl + ((size_t)e * HDIM + nb) * CDIM;
    } else {
        srcA[0] = g_hh + (size_t)(off + r0) * HDIM;
        srcA[1] = g_hl + (size_t)(off + r0) * HDIM;
        srcB[0] = g_woTh + ((size_t)e * CDIM + nb) * HDIM;
        srcB[1] = g_woTl + ((size_t)e * CDIM + nb) * HDIM;
    }

    // loader: each plane-tile = 128 rows x 4 chunks(16B) = 512 chunks
    int lrow = (tid & 511) >> 2;   // with 512 threads: row = tid>>2
    int lch  = tid & 3;

    auto load_buf = [&](int buf, int kc) {
        uint32_t base = sb + buf * BUFB;
        int k0 = kc * 32;
        // A planes: rows beyond rowsLeft zero-filled via src-size 0
        uint32_t szA = (lrow < rowsLeft) ? 16u : 0u;
        int ra = (lrow < rowsLeft) ? lrow : 0;
#pragma unroll
        for (int p = 0; p < 2; p++)
            CP_ASYNC16(base + p * PLANEB + lrow * PITCHB + lch * 16,
                       srcA[p] + (size_t)ra * K + k0 + lch * 8, szA);
#pragma unroll
        for (int p = 0; p < NB; p++)
            CP_ASYNC16(base + (2 + p) * PLANEB + lrow * PITCHB + lch * 16,
                       srcB[p] + (size_t)lrow * K + k0 + lch * 8, 16u);
        CP_COMMIT();
    };

    constexpr int NW = (MODE == 0) ? 2 : 1;       // weight operands
    float acc[NW][2][4][4];
#pragma unroll
    for (int w = 0; w < NW; w++)
#pragma unroll
        for (int a = 0; a < 2; a++)
#pragma unroll
            for (int b = 0; b < 4; b++)
#pragma unroll
                for (int c = 0; c < 4; c++) acc[w][a][b][c] = 0.f;

    load_buf(0, 0);

    // per-warp smem address pieces
    uint32_t aRowOff = (WM * 32 + (lane & 15)) * PITCHB + (lane >> 4) * 16;
    uint32_t bRowOff = (WN * 32 + (lane & 15)) * PITCHB + (lane >> 4) * 16;

    for (int kc = 0; kc < KT; kc++) {
        if (kc + 1 < KT) { load_buf((kc + 1) & 1, kc + 1); CP_WAIT(1); }
        else             { CP_WAIT(0); }
        __syncthreads();

        uint32_t base = sb + (kc & 1) * BUFB;
#pragma unroll
        for (int ks = 0; ks < 2; ks++) {
            uint32_t kOff = ks * 32;              // 16 halfs = 32 bytes
            uint32_t ah[2][4], al[2][4];
#pragma unroll
            for (int mi = 0; mi < 2; mi++) {
                ldsm4(ah[mi], base + aRowOff + mi * 16 * PITCHB + kOff);
                ldsm4(al[mi], base + PLANEB + aRowOff + mi * 16 * PITCHB + kOff);
            }
#pragma unroll
            for (int w = 0; w < NW; w++) {
                uint32_t bh[2][4], bl[2][4];
                uint32_t bBase = base + (2 + 2 * w) * PLANEB;
#pragma unroll
                for (int ng = 0; ng < 2; ng++) {
                    ldsm4(bh[ng], bBase + bRowOff + ng * 16 * PITCHB + kOff);
                    ldsm4(bl[ng], bBase + PLANEB + bRowOff + ng * 16 * PITCHB + kOff);
                }
#pragma unroll
                for (int mi = 0; mi < 2; mi++)
#pragma unroll
                    for (int nj = 0; nj < 4; nj++) {
                        int ng = nj >> 1, ix = nj & 1;
                        mma16816(acc[w][mi][nj], ah[mi], bh[ng][ix], bh[ng][ix + 2]);
                        mma16816(acc[w][mi][nj], al[mi], bh[ng][ix], bh[ng][ix + 2]);
                        mma16816(acc[w][mi][nj], ah[mi], bl[ng][ix], bl[ng][ix + 2]);
                    }
            }
        }
        __syncthreads();
    }

    // ---- epilogue ----
    int grb = off + r0;
#pragma unroll
    for (int mi = 0; mi < 2; mi++) {
#pragma unroll
        for (int half = 0; half < 2; half++) {
            int r = WM * 32 + mi * 16 + gq + half * 8;
            if (r >= rowsLeft) continue;
            size_t grow = (size_t)(grb + r);
#pragma unroll
            for (int nj = 0; nj < 4; nj++) {
                int c = nb + WN * 32 + nj * 8 + tg * 2;
                if (MODE == 0) {
                    float gt0 = acc[0][mi][nj][half * 2 + 0];
                    float gt1 = acc[0][mi][nj][half * 2 + 1];
                    float up0 = acc[1][mi][nj][half * 2 + 0];
                    float up1 = acc[1][mi][nj][half * 2 + 1];
                    float h0 = up0 * gt0 / (1.f + expf(-gt0));
                    float h1 = up1 * gt1 / (1.f + expf(-gt1));
                    __nv_bfloat16 h0h = __float2bfloat16(h0);
                    __nv_bfloat16 h1h = __float2bfloat16(h1);
                    __nv_bfloat16 h0l = __float2bfloat16(h0 - __bfloat162float(h0h));
                    __nv_bfloat16 h1l = __float2bfloat16(h1 - __bfloat162float(h1h));
                    uint32_t uh = ((uint32_t)__bfloat16_as_ushort(h1h) << 16) | __bfloat16_as_ushort(h0h);
                    uint32_t ul = ((uint32_t)__bfloat16_as_ushort(h1l) << 16) | __bfloat16_as_ushort(h0l);
                    *(uint32_t*)&g_hh[grow * HDIM + c] = uh;
                    *(uint32_t*)&g_hl[grow * HDIM + c] = ul;
                } else {
                    float d0 = acc[0][mi][nj][half * 2 + 0];
                    float d1 = acc[0][mi][nj][half * 2 + 1];
                    *(float2*)&g_y[grow * CDIM + c] = make_float2(d0, d1);
                }
            }
        }
    }
}

// ---------------- combine ----------------------------------------------------
__global__ void combine_kernel(float* __restrict__ out) {
    int gid = blockIdx.x * blockDim.x + threadIdx.x;
    int t = gid >> 8;
    int c4 = (gid & 255) * 4;
    int p0 = g_pairidx[2 * t], p1 = g_pairidx[2 * t + 1];
    float w0 = g_wt[p0], w1 = g_wt[p1];
    float4 y0 = *(const float4*)&g_y[(size_t)p0 * CDIM + c4];
    float4 y1 = *(const float4*)&g_y[(size_t)p1 * CDIM + c4];
    float4 o;
    o.x = w0 * y0.x + w1 * y1.x;
    o.y = w0 * y0.y + w1 * y1.y;
    o.z = w0 * y0.z + w1 * y1.z;
    o.w = w0 * y0.w + w1 * y1.w;
    *(float4*)(out + (size_t)t * CDIM + c4) = o;
}

// ---------------- launch -----------------------------------------------------
#define SMEM0 (2 * 6 * PLANEB)   // 122880
#define SMEM2 (2 * 4 * PLANEB)   // 81920

extern "C" void kernel_launch(void* const* d_in, const int* in_sizes, int n_in,
                              void* d_out, int out_size) {
    const float* x      = (const float*)d_in[0];
    const float* w_gate = (const float*)d_in[1];
    const float* wi     = (const float*)d_in[2];
    const float* wg     = (const float*)d_in[3];
    const float* wo     = (const float*)d_in[4];
    float* out = (float*)d_out;

    cudaFuncSetAttribute(moe_mma<0>, cudaFuncAttributeMaxDynamicSharedMemorySize, SMEM0);
    cudaFuncSetAttribute(moe_mma<2>, cudaFuncAttributeMaxDynamicSharedMemorySize, SMEM2);

    gate_kernel<<<NTOK / 8, 256>>>(x, w_gate);
    setup_kernel<<<1, 256>>>();
    gather_split_kernel<<<NPAIR, 256>>>(x);

    dim3 tb(32, 8);
    tsplit_kernel<0><<<dim3(CDIM / 32, HDIM / 32, NEXP), tb>>>(wg, CDIM, HDIM);
    tsplit_kernel<1><<<dim3(CDIM / 32, HDIM / 32, NEXP), tb>>>(wi, CDIM, HDIM);
    tsplit_kernel<2><<<dim3(HDIM / 32, CDIM / 32, NEXP), tb>>>(wo, HDIM, CDIM);

    moe_mma<0><<<dim3(MT_MAX, HDIM / 128), 512, SMEM0>>>();
    moe_mma<2><<<dim3(MT_MAX, CDIM / 128), 512, SMEM2>>>();

    combine_kernel<<<NTOK * (CDIM / 4) / 256, 256>>>(out);
}

// round 8
// speedup vs baseline: 2.1633x; 1.0050x over previous
#include <cuda_runtime.h>
#include <cuda_bf16.h>
#include <cstdint>
#include <math.h>

// ---------------- problem constants ------------------------------------------
#define NTOK 8192
#define CDIM 1024
#define HDIM 2048
#define NEXP 8
#define NPAIR (NTOK * 2)
#define BM 128
#define MT_MAX 136

// ---------------- scratch ----------------------------------------------------
__device__ __nv_bfloat16 g_axh[(size_t)NPAIR * CDIM];
__device__ __nv_bfloat16 g_axl[(size_t)NPAIR * CDIM];
__device__ __nv_bfloat16 g_wgTh[(size_t)NEXP * HDIM * CDIM];
__device__ __nv_bfloat16 g_wgTl[(size_t)NEXP * HDIM * CDIM];
__device__ __nv_bfloat16 g_wiTh[(size_t)NEXP * HDIM * CDIM];
__device__ __nv_bfloat16 g_wiTl[(size_t)NEXP * HDIM * CDIM];
__device__ __nv_bfloat16 g_woTh[(size_t)NEXP * CDIM * HDIM];
__device__ __nv_bfloat16 g_woTl[(size_t)NEXP * CDIM * HDIM];
__device__ __nv_bfloat16 g_hh[(size_t)NPAIR * HDIM];
__device__ __nv_bfloat16 g_hl[(size_t)NPAIR * HDIM];
__device__ float         g_y[(size_t)NPAIR * CDIM];

__device__ int   g_sel[NTOK * 2];
__device__ float g_selw[NTOK * 2];
__device__ int   g_tok[NPAIR];
__device__ float g_wt[NPAIR];
__device__ int   g_pairidx[NTOK * 2];
__device__ int   g_cnt[NEXP];
__device__ int   g_off[NEXP];
__device__ int   g_tileE[MT_MAX];
__device__ int   g_tileR[MT_MAX];
__device__ int   g_numTiles;

// ---------------- PTX helpers -------------------------------------------------
__device__ __forceinline__ uint32_t smem_u32(const void* p) {
    uint32_t a;
    asm("{ .reg .u64 t; cvta.to.shared.u64 t, %1; cvt.u32.u64 %0, t; }" : "=r"(a) : "l"(p));
    return a;
}
__device__ __forceinline__ void ldsm4(uint32_t* r, uint32_t addr) {
    asm volatile("ldmatrix.sync.aligned.m8n8.x4.shared.b16 {%0,%1,%2,%3}, [%4];"
                 : "=r"(r[0]), "=r"(r[1]), "=r"(r[2]), "=r"(r[3]) : "r"(addr));
}
__device__ __forceinline__ void mma16816(float* d, const uint32_t* a, uint32_t b0, uint32_t b1) {
    asm volatile("mma.sync.aligned.m16n8k16.row.col.f32.bf16.bf16.f32 "
                 "{%0,%1,%2,%3}, {%4,%5,%6,%7}, {%8,%9}, {%0,%1,%2,%3};"
                 : "+f"(d[0]), "+f"(d[1]), "+f"(d[2]), "+f"(d[3])
                 : "r"(a[0]), "r"(a[1]), "r"(a[2]), "r"(a[3]), "r"(b0), "r"(b1));
}
#define CP_ASYNC16(dst, src, sz) \
    asm volatile("cp.async.cg.shared.global [%0], [%1], 16, %2;" :: "r"(dst), "l"(src), "r"(sz) : "memory")
#define CP_COMMIT() asm volatile("cp.async.commit_group;" ::: "memory")
#define CP_WAIT(n)  asm volatile("cp.async.wait_group %0;" :: "n"(n) : "memory")

// ---------------- gating -----------------------------------------------------
__global__ void gate_kernel(const float* __restrict__ x, const float* __restrict__ wgate) {
    int warp = (blockIdx.x * blockDim.x + threadIdx.x) >> 5;
    int lane = threadIdx.x & 31;
    if (warp >= NTOK) return;
    const float* xr = x + (size_t)warp * CDIM;
    float acc[NEXP];
#pragma unroll
    for (int e = 0; e < NEXP; e++) acc[e] = 0.f;
    for (int i = lane * 4; i < CDIM; i += 128) {
        float4 xv = *(const float4*)(xr + i);
        float xs[4] = {xv.x, xv.y, xv.z, xv.w};
#pragma unroll
        for (int j = 0; j < 4; j++) {
            const float* wr = wgate + (size_t)(i + j) * NEXP;
#pragma unroll
            for (int e = 0; e < NEXP; e++) acc[e] += xs[j] * wr[e];
        }
    }
#pragma unroll
    for (int e = 0; e < NEXP; e++)
#pragma unroll
        for (int d = 16; d > 0; d >>= 1) acc[e] += __shfl_down_sync(0xffffffffu, acc[e], d);
    if (lane == 0) {
        float m = acc[0];
#pragma unroll
        for (int e = 1; e < NEXP; e++) m = fmaxf(m, acc[e]);
        float p[NEXP]; float s = 0.f;
#pragma unroll
        for (int e = 0; e < NEXP; e++) { p[e] = expf(acc[e] - m); s += p[e]; }
        float inv = 1.f / s;
#pragma unroll
        for (int e = 0; e < NEXP; e++) p[e] *= inv;
        int i1 = 0;
#pragma unroll
        for (int e = 1; e < NEXP; e++) if (p[e] > p[i1]) i1 = e;
        int i2 = (i1 == 0) ? 1 : 0;
#pragma unroll
        for (int e = 0; e < NEXP; e++) if (e != i1 && p[e] > p[i2]) i2 = e;
        g_sel[2 * warp] = i1;     g_selw[2 * warp] = p[i1];
        g_sel[2 * warp + 1] = i2; g_selw[2 * warp + 1] = p[i2];
    }
}

// ---------------- routing build ----------------------------------------------
__global__ void setup_kernel() {
    __shared__ int scnt[NEXP], soff[NEXP], wsum[8];
    __shared__ int carry_s;
    int tid = threadIdx.x, lane = tid & 31, wid = tid >> 5;
    if (tid < NEXP) scnt[tid] = 0;
    __syncthreads();
    for (int t = tid; t < NTOK; t += 256) {
        atomicAdd(&scnt[g_sel[2 * t]], 1);
        atomicAdd(&scnt[g_sel[2 * t + 1]], 1);
    }
    __syncthreads();
    if (tid == 0) {
        int o = 0, nt = 0;
        for (int e = 0; e < NEXP; e++) {
            g_cnt[e] = scnt[e]; g_off[e] = o; soff[e] = o;
            for (int r = 0; r < scnt[e]; r += BM) { g_tileE[nt] = e; g_tileR[nt] = r; nt++; }
            o += scnt[e];
        }
        g_numTiles = nt;
    }
    __syncthreads();
    for (int e = 0; e < NEXP; e++) {
        if (tid == 0) carry_s = 0;
        __syncthreads();
        int base_off = soff[e];
        for (int base = 0; base < NTOK; base += 256) {
            int t = base + tid;
            int slot = (g_sel[2 * t] == e) ? 0 : ((g_sel[2 * t + 1] == e) ? 1 : -1);
            int f = (slot >= 0) ? 1 : 0;
            int v = f;
#pragma unroll
            for (int d = 1; d < 32; d <<= 1) {
                int u = __shfl_up_sync(0xffffffffu, v, d);
                if (lane >= d) v += u;
            }
            if (lane == 31) wsum[wid] = v;
            __syncthreads();
            int wbase = 0, tot = 0;
#pragma unroll
            for (int w = 0; w < 8; w++) { if (w < wid) wbase += wsum[w]; tot += wsum[w]; }
            if (f) {
                int p = base_off + carry_s + wbase + v - 1;
                g_tok[p] = t;
                g_wt[p] = g_selw[2 * t + slot];
                g_pairidx[2 * t + slot] = p;
            }
            __syncthreads();
            if (tid == 0) carry_s += tot;
            __syncthreads();
        }
    }
}

// ---------------- weight transpose + split (device-selected dst) --------------
template <int W>
__global__ void tsplit_kernel(const float* __restrict__ src, int K, int S) {
    __nv_bfloat16* dsth = (W == 0) ? g_wgTh : (W == 1) ? g_wiTh : g_woTh;
    __nv_bfloat16* dstl = (W == 0) ? g_wgTl : (W == 1) ? g_wiTl : g_woTl;
    __shared__ float t[32][33];
    int e = blockIdx.z;
    int k0 = blockIdx.x * 32, s0 = blockIdx.y * 32;
    const float* sp = src + (size_t)e * K * S;
    int tx = threadIdx.x, ty = threadIdx.y;
#pragma unroll
    for (int j = 0; j < 32; j += 8)
        t[ty + j][tx] = sp[(size_t)(k0 + ty + j) * S + s0 + tx];
    __syncthreads();
    size_t dbase = (size_t)e * S * K;
#pragma unroll
    for (int j = 0; j < 32; j += 8) {
        float v = t[tx][ty + j];
        __nv_bfloat16 hi = __float2bfloat16(v);
        __nv_bfloat16 lo = __float2bfloat16(v - __bfloat162float(hi));
        size_t o = dbase + (size_t)(s0 + ty + j) * K + k0 + tx;
        dsth[o] = hi; dstl[o] = lo;
    }
}

// ---------------- activation gather + split -----------------------------------
__global__ void gather_split_kernel(const float* __restrict__ x) {
    int p = blockIdx.x;
    int t = g_tok[p];
    const float* src = x + (size_t)t * CDIM;
    size_t dst = (size_t)p * CDIM;
    for (int i = threadIdx.x; i < CDIM; i += 256) {
        float v = src[i];
        __nv_bfloat16 hi = __float2bfloat16(v);
        g_axh[dst + i] = hi;
        g_axl[dst + i] = __float2bfloat16(v - __bfloat162float(hi));
    }
}

// ---------------- split-bf16 mma GEMM, 128x128 tile, 3-stage cp.async ---------
// MODE 0 (fused): gate = ax@wgT^T, up = ax@wiT^T, h = silu(gate)*up -> g_hh/g_hl
// MODE 2 (down):  y = h@woT^T -> g_y
// 512 threads, warp grid 4m x 4n, warp tile 32x32. Pitch 80 B.
// One __syncthreads per 32-K chunk; 2 chunks always in flight.
#define PITCHB 80
#define PLANEB (128 * PITCHB)   // 10240
#define STAGES 3

template <int MODE>
__global__ void __launch_bounds__(512, 1)
moe_mma() {
    constexpr int K = (MODE == 0) ? CDIM : HDIM;
    constexpr int KT = K / 32;
    constexpr int NB = (MODE == 0) ? 4 : 2;       // B plane-tiles per stage
    constexpr int BUFB = (2 + NB) * PLANEB;

    extern __shared__ char smem[];
    uint32_t sb = smem_u32(smem);

    int bx = blockIdx.x;
    if (bx >= g_numTiles) return;
    int by = blockIdx.y;
    int e = g_tileE[bx], r0 = g_tileR[bx], off = g_off[e];
    int rowsLeft = g_cnt[e] - r0;
    if (rowsLeft > 128) rowsLeft = 128;
    int nb = by * 128;

    int tid = threadIdx.x, wid = tid >> 5, lane = tid & 31;
    int WM = wid & 3, WN = wid >> 2;
    int gq = lane >> 2, tg = lane & 3;

    const __nv_bfloat16* srcA[2];
    const __nv_bfloat16* srcB[4];
    if (MODE == 0) {
        srcA[0] = g_axh + (size_t)(off + r0) * CDIM;
        srcA[1] = g_axl + (size_t)(off + r0) * CDIM;
        srcB[0] = g_wgTh + ((size_t)e * HDIM + nb) * CDIM;
        srcB[1] = g_wgTl + ((size_t)e * HDIM + nb) * CDIM;
        srcB[2] = g_wiTh + ((size_t)e * HDIM + nb) * CDIM;
        srcB[3] = g_wiTl + ((size_t)e * HDIM + nb) * CDIM;
    } else {
        srcA[0] = g_hh + (size_t)(off + r0) * HDIM;
        srcA[1] = g_hl + (size_t)(off + r0) * HDIM;
        srcB[0] = g_woTh + ((size_t)e * CDIM + nb) * HDIM;
        srcB[1] = g_woTl + ((size_t)e * CDIM + nb) * HDIM;
    }

    int lrow = tid >> 2;
    int lch  = tid & 3;

    auto load_buf = [&](int buf, int kc) {
        uint32_t base = sb + buf * BUFB;
        int k0 = kc * 32;
        uint32_t szA = (lrow < rowsLeft) ? 16u : 0u;
        int ra = (lrow < rowsLeft) ? lrow : 0;
#pragma unroll
        for (int p = 0; p < 2; p++)
            CP_ASYNC16(base + p * PLANEB + lrow * PITCHB + lch * 16,
                       srcA[p] + (size_t)ra * K + k0 + lch * 8, szA);
#pragma unroll
        for (int p = 0; p < NB; p++)
            CP_ASYNC16(base + (2 + p) * PLANEB + lrow * PITCHB + lch * 16,
                       srcB[p] + (size_t)lrow * K + k0 + lch * 8, 16u);
        CP_COMMIT();
    };

    constexpr int NW = (MODE == 0) ? 2 : 1;
    float acc[NW][2][4][4];
#pragma unroll
    for (int w = 0; w < NW; w++)
#pragma unroll
        for (int a = 0; a < 2; a++)
#pragma unroll
            for (int b = 0; b < 4; b++)
#pragma unroll
                for (int c = 0; c < 4; c++) acc[w][a][b][c] = 0.f;

    // prologue: 2 chunks in flight
    load_buf(0, 0);
    load_buf(1, 1);

    uint32_t aRowOff = (WM * 32 + (lane & 15)) * PITCHB + (lane >> 4) * 16;
    uint32_t bRowOff = (WN * 32 + (lane & 15)) * PITCHB + (lane >> 4) * 16;

    int cb = 0;                  // compute buffer = kc % 3
    for (int kc = 0; kc < KT; kc++) {
        if (kc + 1 < KT) { CP_WAIT(1); } else { CP_WAIT(0); }
        __syncthreads();
        // issue chunk kc+2 into buffer (kc+2)%3 == (cb+2)%3 — its previous
        // contents (chunk kc-1) were consumed before the sync above.
        if (kc + 2 < KT) {
            int lb = cb + 2; if (lb >= STAGES) lb -= STAGES;
            load_buf(lb, kc + 2);
        }

        uint32_t base = sb + cb * BUFB;
#pragma unroll
        for (int ks = 0; ks < 2; ks++) {
            uint32_t kOff = ks * 32;
            uint32_t ah[2][4], al[2][4];
#pragma unroll
            for (int mi = 0; mi < 2; mi++) {
                ldsm4(ah[mi], base + aRowOff + mi * 16 * PITCHB + kOff);
                ldsm4(al[mi], base + PLANEB + aRowOff + mi * 16 * PITCHB + kOff);
            }
#pragma unroll
            for (int w = 0; w < NW; w++) {
                uint32_t bh[2][4], bl[2][4];
                uint32_t bBase = base + (2 + 2 * w) * PLANEB;
#pragma unroll
                for (int ng = 0; ng < 2; ng++) {
                    ldsm4(bh[ng], bBase + bRowOff + ng * 16 * PITCHB + kOff);
                    ldsm4(bl[ng], bBase + PLANEB + bRowOff + ng * 16 * PITCHB + kOff);
                }
#pragma unroll
                for (int mi = 0; mi < 2; mi++)
#pragma unroll
                    for (int nj = 0; nj < 4; nj++) {
                        int ng = nj >> 1, ix = nj & 1;
                        mma16816(acc[w][mi][nj], ah[mi], bh[ng][ix], bh[ng][ix + 2]);
                        mma16816(acc[w][mi][nj], al[mi], bh[ng][ix], bh[ng][ix + 2]);
                        mma16816(acc[w][mi][nj], ah[mi], bl[ng][ix], bl[ng][ix + 2]);
                    }
            }
        }
        cb++; if (cb >= STAGES) cb = 0;
        // no trailing sync: next iteration's wait+sync separates buffer reuse
        __syncthreads();
    }

    // ---- epilogue ----
    int grb = off + r0;
#pragma unroll
    for (int mi = 0; mi < 2; mi++) {
#pragma unroll
        for (int half = 0; half < 2; half++) {
            int r = WM * 32 + mi * 16 + gq + half * 8;
            if (r >= rowsLeft) continue;
            size_t grow = (size_t)(grb + r);
#pragma unroll
            for (int nj = 0; nj < 4; nj++) {
                int c = nb + WN * 32 + nj * 8 + tg * 2;
                if (MODE == 0) {
                    float gt0 = acc[0][mi][nj][half * 2 + 0];
                    float gt1 = acc[0][mi][nj][half * 2 + 1];
                    float up0 = acc[1][mi][nj][half * 2 + 0];
                    float up1 = acc[1][mi][nj][half * 2 + 1];
                    float h0 = up0 * gt0 / (1.f + __expf(-gt0));
                    float h1 = up1 * gt1 / (1.f + __expf(-gt1));
                    __nv_bfloat16 h0h = __float2bfloat16(h0);
                    __nv_bfloat16 h1h = __float2bfloat16(h1);
                    __nv_bfloat16 h0l = __float2bfloat16(h0 - __bfloat162float(h0h));
                    __nv_bfloat16 h1l = __float2bfloat16(h1 - __bfloat162float(h1h));
                    uint32_t uh = ((uint32_t)__bfloat16_as_ushort(h1h) << 16) | __bfloat16_as_ushort(h0h);
                    uint32_t ul = ((uint32_t)__bfloat16_as_ushort(h1l) << 16) | __bfloat16_as_ushort(h0l);
                    *(uint32_t*)&g_hh[grow * HDIM + c] = uh;
                    *(uint32_t*)&g_hl[grow * HDIM + c] = ul;
                } else {
                    float d0 = acc[0][mi][nj][half * 2 + 0];
                    float d1 = acc[0][mi][nj][half * 2 + 1];
                    *(float2*)&g_y[grow * CDIM + c] = make_float2(d0, d1);
                }
            }
        }
    }
}

// ---------------- combine ----------------------------------------------------
__global__ void combine_kernel(float* __restrict__ out) {
    int gid = blockIdx.x * blockDim.x + threadIdx.x;
    int t = gid >> 8;
    int c4 = (gid & 255) * 4;
    int p0 = g_pairidx[2 * t], p1 = g_pairidx[2 * t + 1];
    float w0 = g_wt[p0], w1 = g_wt[p1];
    float4 y0 = *(const float4*)&g_y[(size_t)p0 * CDIM + c4];
    float4 y1 = *(const float4*)&g_y[(size_t)p1 * CDIM + c4];
    float4 o;
    o.x = w0 * y0.x + w1 * y1.x;
    o.y = w0 * y0.y + w1 * y1.y;
    o.z = w0 * y0.z + w1 * y1.z;
    o.w = w0 * y0.w + w1 * y1.w;
    *(float4*)(out + (size_t)t * CDIM + c4) = o;
}

// ---------------- launch -----------------------------------------------------
#define SMEM0 (STAGES * 6 * PLANEB)   // 184320
#define SMEM2 (STAGES * 4 * PLANEB)   // 122880

extern "C" void kernel_launch(void* const* d_in, const int* in_sizes, int n_in,
                              void* d_out, int out_size) {
    const float* x      = (const float*)d_in[0];
    const float* w_gate = (const float*)d_in[1];
    const float* wi     = (const float*)d_in[2];
    const float* wg     = (const float*)d_in[3];
    const float* wo     = (const float*)d_in[4];
    float* out = (float*)d_out;

    cudaFuncSetAttribute(moe_mma<0>, cudaFuncAttributeMaxDynamicSharedMemorySize, SMEM0);
    cudaFuncSetAttribute(moe_mma<2>, cudaFuncAttributeMaxDynamicSharedMemorySize, SMEM2);

    gate_kernel<<<NTOK / 8, 256>>>(x, w_gate);
    setup_kernel<<<1, 256>>>();
    gather_split_kernel<<<NPAIR, 256>>>(x);

    dim3 tb(32, 8);
    tsplit_kernel<0><<<dim3(CDIM / 32, HDIM / 32, NEXP), tb>>>(wg, CDIM, HDIM);
    tsplit_kernel<1><<<dim3(CDIM / 32, HDIM / 32, NEXP), tb>>>(wi, CDIM, HDIM);
    tsplit_kernel<2><<<dim3(HDIM / 32, CDIM / 32, NEXP), tb>>>(wo, HDIM, CDIM);

    moe_mma<0><<<dim3(MT_MAX, HDIM / 128), 512, SMEM0>>>();
    moe_mma<2><<<dim3(MT_MAX, CDIM / 128), 512, SMEM2>>>();

    combine_kernel<<<NTOK * (CDIM / 4) / 256, 256>>>(out);
}